// round 6
// baseline (speedup 1.0000x reference)
#include <cuda_runtime.h>

#define H 2048
#define W 2048
#define BW 32
#define TILE_H 16            // output rows per warp tile
#define WROWS (TILE_H + 6)   // 22 h-sum rows per warp
#define NWARPS 4             // warps per block, stacked vertically
#define NTASK (WROWS * 8)    // 176 interior h-pass tasks per warp

__global__ __launch_bounds__(128)
void plane_fit_kernel(const float* __restrict__ x, float* __restrict__ out) {
    // Per-warp private horizontal sums: .x = 7-tap box, .y = 7-tap ramp
    __shared__ float2 hbr_all[NWARPS][WROWS][BW];

    const int tx  = threadIdx.x & 31;   // lane
    const int wid = threadIdx.x >> 5;   // warp in block
    const int bx  = blockIdx.x * BW;
    const int by  = (blockIdx.y * NWARPS + wid) * TILE_H;

    float2 (* const hb)[BW] = hbr_all[wid];

    const bool interior = (bx != 0) && (bx != W - BW) &&
                          (by != 0) && (by + TILE_H != H);

    if (interior) {
        // ---- Horizontal pass: 176 tasks = 5 full warp rounds + 16 extras ----
        auto htask = [&](int t) {
            int r = t >> 3;
            int cg = t & 7;
            int gi = by + r - 3;                     // in-bounds (interior in y)
            const float4* p = reinterpret_cast<const float4*>(
                x + (size_t)gi * W + (bx + cg * 4 - 4));   // 16B-aligned
            float4 A = p[0], B = p[1], C = p[2];
            float v1 = A.y, v2 = A.z, v3 = A.w;
            float v4 = B.x, v5 = B.y, v6 = B.z, v7 = B.w;
            float v8 = C.x, v9 = C.y, v10 = C.z;

            float s0 = ((v1 + v2) + (v3 + v4)) + ((v5 + v6) + v7);
            float s1 = s0 - v1 + v8;
            float s2 = s1 - v2 + v9;
            float s3 = s2 - v3 + v10;

            float r0 = fmaf(3.f, v7 - v1, fmaf(2.f, v6 - v2, v5 - v3));
            float r1 = fmaf(3.f, v8 - v2, fmaf(2.f, v7 - v3, v6 - v4));
            float r2 = fmaf(3.f, v9 - v3, fmaf(2.f, v8 - v4, v7 - v5));
            float r3 = fmaf(3.f, v10 - v4, fmaf(2.f, v9 - v5, v8 - v6));

            float4* dst = reinterpret_cast<float4*>(&hb[r][cg * 4]);
            dst[0] = make_float4(s0, r0, s1, r1);
            dst[1] = make_float4(s2, r2, s3, r3);
        };
        htask(tx);
        htask(tx + 32);
        htask(tx + 64);
        htask(tx + 96);
        htask(tx + 128);
        if (tx < NTASK - 160) htask(tx + 160);
    } else {
        // ---- Border warp tiles: scalar path with edge clamping ----
        #pragma unroll 1
        for (int t = tx; t < WROWS * BW; t += 32) {
            int r = t >> 5;
            int c = t & 31;
            int gi = by + r - 3;
            gi = gi < 0 ? 0 : (gi > H - 1 ? H - 1 : gi);
            const float* row = x + (size_t)gi * W;
            float s = 0.f, rmp = 0.f;
            #pragma unroll
            for (int d = 0; d < 7; d++) {
                int gj = bx + c + d - 3;
                gj = gj < 0 ? 0 : (gj > W - 1 ? W - 1 : gj);
                float v = row[gj];
                s += v;
                rmp += (float)(d - 3) * v;
            }
            hb[r][c] = make_float2(s, rmp);
        }
    }
    __syncwarp();   // warp-private smem: no block barrier needed

    // ---- Vertical pass: sliding 7-row circular window, 16 rows per lane ----
    float2 w[7];
    #pragma unroll
    for (int k = 0; k < 7; k++) w[k] = hb[k][tx];

    float sb = 0.f, sbr = 0.f, srb = 0.f;
    #pragma unroll
    for (int k = 0; k < 7; k++) {
        sb  += w[k].x;
        sbr += w[k].y;
        srb += (float)(k - 3) * w[k].x;
    }

    const float inv196 = 1.0f / 196.0f;
    const float inv49  = 1.0f / 49.0f;

    // Warp-transpose store: dest lane l = 3q+m writes float4 at offset 16*l
    // of the 384B row segment; sources are lanes 4q+m and 4q+m+1.
    const int q  = tx / 3;
    const int m  = tx - 3 * q;
    const int sA = 4 * q + m;
    const int sB = sA + 1;
    const bool writer = (tx < 24);
    float* const rowbase = out + ((size_t)by * W + bx) * 3 + tx * 4;

    #pragma unroll
    for (int i = 0; i < TILE_H; i++) {
        float c0 = sbr * inv196;   // horizontal-ramp, vertical-box
        float c1 = srb * inv196;   // horizontal-box, vertical-ramp
        float c2 = sb  * inv49;    // mean

        float a0 = __shfl_sync(0xffffffffu, c0, sA);
        float a1 = __shfl_sync(0xffffffffu, c1, sA);
        float a2 = __shfl_sync(0xffffffffu, c2, sA);
        float b0 = __shfl_sync(0xffffffffu, c0, sB);
        float b1 = __shfl_sync(0xffffffffu, c1, sB);
        float b2 = __shfl_sync(0xffffffffu, c2, sB);

        float w0 = (m == 0) ? a0 : ((m == 1) ? a1 : a2);
        float w1 = (m == 0) ? a1 : ((m == 1) ? a2 : b0);
        float w2 = (m == 0) ? a2 : ((m == 1) ? b0 : b1);
        float w3 = (m == 0) ? b0 : ((m == 1) ? b1 : b2);

        if (writer) {
            *reinterpret_cast<float4*>(rowbase + (size_t)i * W * 3) =
                make_float4(w0, w1, w2, w3);
        }

        if (i < TILE_H - 1) {
            float2 nw = hb[7 + i][tx];      // one fresh row from warp smem
            float2 ow = w[i % 7];           // circular window, static after unroll
            srb = srb - sb + fmaf(4.f, ow.x, 3.f * nw.x);
            sb  = sb + (nw.x - ow.x);
            sbr = sbr + (nw.y - ow.y);
            w[i % 7] = nw;
        }
    }
}

extern "C" void kernel_launch(void* const* d_in, const int* in_sizes, int n_in,
                              void* d_out, int out_size) {
    const float* x = (const float*)d_in[0];
    float* out = (float*)d_out;
    dim3 block(128);
    dim3 grid(W / BW, H / (TILE_H * NWARPS));   // 64 x 32 = 2048 blocks
    plane_fit_kernel<<<grid, block>>>(x, out);
}

// round 7
// speedup vs baseline: 1.2401x; 1.2401x over previous
#include <cuda_runtime.h>

#define H 2048
#define W 2048
#define BW 32
#define BH 64
#define RPT 8            // output rows per thread
#define TROWS (BH + 6)   // 70 horizontal-sum rows per block

__global__ __launch_bounds__(256)
void plane_fit_kernel(const float* __restrict__ x, float* __restrict__ out) {
    // Interleaved horizontal sums: .x = 7-tap box, .y = 7-tap ramp
    __shared__ float2 hbr[TROWS][BW];

    const int tx = threadIdx.x;          // 0..31 (lane)
    const int ty = threadIdx.y;          // 0..7
    const int tid = ty * 32 + tx;
    const int bx = blockIdx.x * BW;
    const int by = blockIdx.y * BH;

    const bool interior = (bx != 0) && (bx != W - BW) && (by != 0) && (by != H - BH);

    if (interior) {
        // ---- Horizontal pass, vectorized, straight from global ----
        #pragma unroll 1
        for (int t = tid; t < TROWS * 8; t += 256) {
            int r = t >> 3;
            int cg = t & 7;
            int gi = by + r - 3;                     // in-bounds (interior in y)
            const float4* p = reinterpret_cast<const float4*>(
                x + (size_t)gi * W + (bx + cg * 4 - 4));   // 16B-aligned
            float4 A = p[0], B = p[1], C = p[2];
            float v1 = A.y, v2 = A.z, v3 = A.w;
            float v4 = B.x, v5 = B.y, v6 = B.z, v7 = B.w;
            float v8 = C.x, v9 = C.y, v10 = C.z;

            float s0 = ((v1 + v2) + (v3 + v4)) + ((v5 + v6) + v7);
            float s1 = s0 - v1 + v8;
            float s2 = s1 - v2 + v9;
            float s3 = s2 - v3 + v10;

            float r0 = fmaf(3.f, v7 - v1, fmaf(2.f, v6 - v2, v5 - v3));
            float r1 = fmaf(3.f, v8 - v2, fmaf(2.f, v7 - v3, v6 - v4));
            float r2 = fmaf(3.f, v9 - v3, fmaf(2.f, v8 - v4, v7 - v5));
            float r3 = fmaf(3.f, v10 - v4, fmaf(2.f, v9 - v5, v8 - v6));

            float4* dst = reinterpret_cast<float4*>(&hbr[r][cg * 4]);
            dst[0] = make_float4(s0, r0, s1, r1);
            dst[1] = make_float4(s2, r2, s3, r3);
        }
    } else {
        // ---- Border blocks: scalar path with edge clamping ----
        #pragma unroll 1
        for (int t = tid; t < TROWS * BW; t += 256) {
            int r = t >> 5;
            int c = t & 31;
            int gi = by + r - 3;
            gi = gi < 0 ? 0 : (gi > H - 1 ? H - 1 : gi);
            const float* row = x + (size_t)gi * W;
            float s = 0.f, rmp = 0.f;
            #pragma unroll
            for (int d = 0; d < 7; d++) {
                int gj = bx + c + d - 3;
                gj = gj < 0 ? 0 : (gj > W - 1 ? W - 1 : gj);
                float v = row[gj];
                s += v;
                rmp += (float)(d - 3) * v;
            }
            hbr[r][c] = make_float2(s, rmp);
        }
    }
    __syncthreads();

    // ---- Permuted column ownership (3-shuffle store transpose) ----
    // Writer lane l (<24) stores the float4 at byte offset 16*l of the 384B
    // output row segment; it needs coefficients of pixel columns sA=4q+m and
    // sA+1 (q=l/3, m=l%3). Assign lane l<24 to own column sA itself, and
    // lanes 24..31 to own the leftover columns 4k+3. Then the neighbor pixel
    // is owned by lane l+1 (m=0,1) or lane 24+q (m=2): ONE shuffle source.
    const int q = tx / 3;                 // meaningful for tx<24
    const int m = tx - 3 * q;
    const int col = (tx < 24) ? (4 * q + m) : (4 * (tx - 24) + 3);
    const int nbr = (tx < 24) ? ((m == 2) ? (24 + q) : (tx + 1)) : 0;
    const bool writer = (tx < 24);

    // ---- Vertical pass: sliding 7-row window on owned column ----
    const int r0 = ty * RPT;
    float2 w[7];
    #pragma unroll
    for (int k = 0; k < 7; k++) w[k] = hbr[r0 + k][col];

    float sb = 0.f, sbr = 0.f, srb = 0.f;
    #pragma unroll
    for (int k = 0; k < 7; k++) {
        sb  += w[k].x;
        sbr += w[k].y;
        srb += (float)(k - 3) * w[k].x;
    }

    const float inv196 = 1.0f / 196.0f;
    const float inv49  = 1.0f / 49.0f;
    float* const rowbase = out + ((size_t)(by + r0) * W + bx) * 3 + tx * 4;

    #pragma unroll
    for (int i = 0; i < RPT; i++) {
        float c0 = sbr * inv196;   // horizontal-ramp, vertical-box
        float c1 = srb * inv196;   // horizontal-box, vertical-ramp
        float c2 = sb  * inv49;    // mean

        float n0 = __shfl_sync(0xffffffffu, c0, nbr);
        float n1 = __shfl_sync(0xffffffffu, c1, nbr);
        float n2 = __shfl_sync(0xffffffffu, c2, nbr);

        // element layout per m:
        //   m=0: [c0 c1 c2 n0]   m=1: [c1 c2 n0 n1]   m=2: [c2 n0 n1 n2]
        float w0 = (m == 0) ? c0 : ((m == 1) ? c1 : c2);
        float w1 = (m == 0) ? c1 : ((m == 1) ? c2 : n0);
        float w2 = (m == 0) ? c2 : ((m == 1) ? n0 : n1);
        float w3 = (m == 0) ? n0 : ((m == 1) ? n1 : n2);

        if (writer) {
            *reinterpret_cast<float4*>(rowbase + (size_t)i * W * 3) =
                make_float4(w0, w1, w2, w3);
        }

        if (i < RPT - 1) {
            float2 nw = hbr[r0 + 7 + i][col];   // one fresh row from smem
            float2 ow = w[i];                   // static index after unroll
            srb = srb - sb + fmaf(4.f, ow.x, 3.f * nw.x);
            sb  = sb + (nw.x - ow.x);
            sbr = sbr + (nw.y - ow.y);
            w[i] = nw;
        }
    }
}

extern "C" void kernel_launch(void* const* d_in, const int* in_sizes, int n_in,
                              void* d_out, int out_size) {
    const float* x = (const float*)d_in[0];
    float* out = (float*)d_out;
    dim3 block(32, 8);
    dim3 grid(W / BW, H / BH);   // 64 x 32 = 2048 blocks
    plane_fit_kernel<<<grid, block>>>(x, out);
}